// round 4
// baseline (speedup 1.0000x reference)
#include <cuda_runtime.h>

#define CIN  3
#define COUT 16
#define DIN  64
#define HIN  64
#define WIN  64
#define OD   62
#define OH   62
#define OW   62

typedef unsigned long long ull;

__device__ __forceinline__ void fma2(ull& acc, ull x, ull w) {
    asm("fma.rn.f32x2 %0, %1, %2, %0;" : "+l"(acc) : "l"(x), "l"(w));
}
__device__ __forceinline__ ull rep2(float a) {
    ull r;
    asm("mov.b64 %0, {%1, %1};" : "=l"(r) : "f"(a));
    return r;
}
__device__ __forceinline__ float2 unpk(ull v) {
    float2 r;
    asm("mov.b64 {%0, %1}, %2;" : "=f"(r.x), "=f"(r.y) : "l"(v));
    return r;
}

// Fused Conv3d(3->16,k=3,valid) + bias + min over D + softmax over C.
// One thread = (n, h', w', channel-group of 8). f32x2 accumulators over
// channel pairs, depth tile of 4, and a one-iteration-ahead LDG prefetch
// (also across depth tiles) so FMA blocks hide all load latency.
__global__ __launch_bounds__(128, 4)
void fused_conv_min_softmax(const float* __restrict__ x,
                            const float* __restrict__ wgt,
                            const float* __restrict__ bias,
                            float* __restrict__ out)
{
    // Weights transposed to [pos(81)][c(16)]; adjacent channels = f32x2 pairs.
    __shared__ ull   wsp[81 * 8];
    __shared__ float bsh[16];
    __shared__ float sred[2][64];
    float* wsf = (float*)wsp;

    const int tid = threadIdx.x;
    for (int i = tid; i < 81 * 16; i += 128) {
        const int c   = i & 15;
        const int pos = i >> 4;
        wsf[i] = wgt[c * 81 + pos];
    }
    if (tid < 16) bsh[tid] = bias[tid];
    __syncthreads();

    const int cg = tid >> 6;          // channel group 0/1
    const int wl = tid & 63;
    const bool active = (wl < OW);
    const int w = active ? wl : 0;    // clamp for safe addressing

    const int h = blockIdx.x;         // 0..61
    const int n = blockIdx.y;         // 0..15

    float mval[8];
#pragma unroll
    for (int c = 0; c < 8; c++) mval[c] = 3.402823466e38f;

    const size_t HW = (size_t)HIN * WIN;
    const float* xn = x + (size_t)n * CIN * DIN * HW;

    // Prefetch rows for tile 0, body 0 (ci=0, kh=0, d0=0).
    float pf[18];
    {
        const float* rp0 = xn + (size_t)h * WIN + w;
#pragma unroll
        for (int r = 0; r < 6; r++) {
            const float* rp = rp0 + (size_t)r * HW;
            pf[3 * r] = rp[0]; pf[3 * r + 1] = rp[1]; pf[3 * r + 2] = rp[2];
        }
    }

    // 16 depth tiles of 4: d0 = 0,4,...,56, then 58 (overlap; min idempotent)
    for (int t = 0; t < 16; t++) {
        const int d0  = (t < 15) ? (t << 2) : 58;
        const int d0n = (t < 14) ? ((t + 1) << 2) : 58;

        ull acc[4][4];
#pragma unroll
        for (int d = 0; d < 4; d++)
#pragma unroll
            for (int pr = 0; pr < 4; pr++) acc[d][pr] = 0ull;

        const float* row = xn + ((size_t)d0 * HIN + h) * WIN + w;
        int wbase = cg * 4;   // ull index into wsp for (ci,kh) tap base
        int khc   = 0;

        // Flattened (ci,kh) loop: it = ci*3 + kh
#pragma unroll 1
        for (int it = 0; it < 9; it++) {
            // Convert current prefetch buffer to packed {x,x}
            ull xr[18];
#pragma unroll
            for (int j = 0; j < 18; j++) xr[j] = rep2(pf[j]);

            // Prefetch next body (or next tile's first body) — overlaps FMA block
            const float* nrow;
            if (it < 8) {
                nrow = (khc == 2) ? (row + ((size_t)DIN * HW - 2 * WIN))
                                  : (row + WIN);
            } else {
                nrow = xn + ((size_t)d0n * HIN + h) * WIN + w;
            }
#pragma unroll
            for (int r = 0; r < 6; r++) {
                const float* rp = nrow + (size_t)r * HW;
                pf[3 * r] = rp[0]; pf[3 * r + 1] = rp[1]; pf[3 * r + 2] = rp[2];
            }

            // 9 taps x 4 channel-pairs x 4 depths = 144 packed FMAs
#pragma unroll
            for (int kd = 0; kd < 3; kd++) {
#pragma unroll
                for (int kw = 0; kw < 3; kw++) {
                    const ull* wrow = &wsp[wbase + (kd * 9 + kw) * 8];
#pragma unroll
                    for (int pr = 0; pr < 4; pr++) {
                        const ull wv = wrow[pr];
                        fma2(acc[0][pr], xr[(kd + 0) * 3 + kw], wv);
                        fma2(acc[1][pr], xr[(kd + 1) * 3 + kw], wv);
                        fma2(acc[2][pr], xr[(kd + 2) * 3 + kw], wv);
                        fma2(acc[3][pr], xr[(kd + 3) * 3 + kw], wv);
                    }
                }
            }

            row = nrow;
            if (khc == 2) { khc = 0; wbase += 168; }  // kh wrap: ci+1
            else          { khc++;   wbase += 24;  }  // kh+1
        }

#pragma unroll
        for (int d = 0; d < 4; d++)
#pragma unroll
            for (int pr = 0; pr < 4; pr++) {
                const float2 v = unpk(acc[d][pr]);
                mval[2 * pr]     = fminf(mval[2 * pr],     v.x);
                mval[2 * pr + 1] = fminf(mval[2 * pr + 1], v.y);
            }
    }

    // bias + softmax over 16 channels, split across 2 threads (cg 0/1)
    float v[8];
    float mx = -3.402823466e38f;
#pragma unroll
    for (int c = 0; c < 8; c++) {
        v[c] = mval[c] + bsh[cg * 8 + c];
        mx = fmaxf(mx, v[c]);
    }
    sred[cg][wl] = mx;
    __syncthreads();
    mx = fmaxf(sred[0][wl], sred[1][wl]);
    __syncthreads();

    float s = 0.f;
#pragma unroll
    for (int c = 0; c < 8; c++) {
        v[c] = __expf(v[c] - mx);
        s += v[c];
    }
    sred[cg][wl] = s;
    __syncthreads();
    const float inv = 1.0f / (sred[0][wl] + sred[1][wl]);

    if (active) {
        const size_t hw = (size_t)h * OW + w;
#pragma unroll
        for (int c = 0; c < 8; c++) {
            out[((size_t)(n * COUT + cg * 8 + c) * OH * OW) + hw] = v[c] * inv;
        }
    }
}

extern "C" void kernel_launch(void* const* d_in, const int* in_sizes, int n_in,
                              void* d_out, int out_size)
{
    const float* x    = (const float*)d_in[0];  // [16,3,64,64,64]
    const float* wgt  = (const float*)d_in[1];  // [16,3,3,3,3]
    const float* bias = (const float*)d_in[2];  // [16]
    float* out = (float*)d_out;                 // [16,16,62,62]

    dim3 grid(OH, 16);   // (h', n)
    dim3 block(128);     // 64 w-lanes x 2 channel groups
    fused_conv_min_softmax<<<grid, block>>>(x, wgt, bias, out);
}

// round 5
// speedup vs baseline: 1.0201x; 1.0201x over previous
#include <cuda_runtime.h>

#define CIN  3
#define COUT 16
#define OD   62
#define OH   62
#define OW   62

typedef unsigned long long ull;

__device__ __forceinline__ void fma2(ull& acc, ull x, ull w) {
    asm("fma.rn.f32x2 %0, %1, %2, %0;" : "+l"(acc) : "l"(x), "l"(w));
}
__device__ __forceinline__ ull rep2(float a) {
    ull r;
    asm("mov.b64 %0, {%1, %1};" : "=l"(r) : "f"(a));
    return r;
}
__device__ __forceinline__ float2 unpk(ull v) {
    float2 r;
    asm("mov.b64 {%0, %1}, %2;" : "=f"(r.x), "=f"(r.y) : "l"(v));
    return r;
}

// Fused Conv3d(3->16,k=3,valid) + bias + min over D + softmax over C.
// Thread = (n, h', w-pair, channel-group of 8). Accumulators f32x2 over
// channel pairs, 2 w-pixels per thread (amortizes weight LDS + x LDG),
// depth tile of 4.
__global__ __launch_bounds__(128)
void fused_conv_min_softmax(const float* __restrict__ x,
                            const float* __restrict__ wgt,
                            const float* __restrict__ bias,
                            float* __restrict__ out)
{
    // Weights transposed to [pos(81)][c(16)]; adjacent channels = f32x2 pairs.
    __shared__ ull    wsp[81 * 8];
    __shared__ float  bsh[16];
    __shared__ float2 sred[2][2][32];
    float* wsf = (float*)wsp;

    const int tid = threadIdx.x;
    for (int i = tid; i < 81 * 16; i += 128) {
        const int c   = i & 15;
        const int pos = i >> 4;
        wsf[i] = wgt[c * 81 + pos];
    }
    if (tid < 16) bsh[tid] = bias[tid];
    __syncthreads();

    const int lane = tid & 31;        // w-pair index (31 pairs; lane 31 dups 30)
    const int cg   = (tid >> 5) & 1;  // channel group (8 channels each)
    const int hs   = tid >> 6;        // h sub-row within block
    const int q    = (lane < 31) ? lane : 30;
    const int w0   = q << 1;          // first of two adjacent output w's
    const int h    = (blockIdx.x << 1) + hs;   // 0..61
    const int n    = blockIdx.y;

    const float* xn = x + (size_t)n * (CIN * 64 * 64 * 64);

    float mval[2][8];
#pragma unroll
    for (int p = 0; p < 2; p++)
#pragma unroll
        for (int c = 0; c < 8; c++) mval[p][c] = 3.402823466e38f;

    // 16 depth tiles of 4: d0 = 0,4,...,56, then 58 (overlap; min idempotent)
    for (int t = 0; t < 16; t++) {
        const int d0 = (t < 15) ? (t << 2) : 58;

        ull acc[4][4][2];   // [depth][channel-pair][pixel]
#pragma unroll
        for (int d = 0; d < 4; d++)
#pragma unroll
            for (int pr = 0; pr < 4; pr++) {
                acc[d][pr][0] = 0ull; acc[d][pr][1] = 0ull;
            }

#pragma unroll 1
        for (int ci = 0; ci < CIN; ci++) {
#pragma unroll 1
            for (int kh = 0; kh < 3; kh++) {
                // x layout [ci][d][y][w]: strides 262144 / 4096 / 64
                const float* rp0 = xn + ci * 262144 + d0 * 4096
                                      + (h + kh) * 64 + w0;

                // 6 depth-rows x 4 consecutive w-floats, replicated {v,v}
                ull xx[6][4];
#pragma unroll
                for (int r = 0; r < 6; r++) {
                    const float2 a = *(const float2*)(rp0 + r * 4096);
                    const float2 b = *(const float2*)(rp0 + r * 4096 + 2);
                    xx[r][0] = rep2(a.x); xx[r][1] = rep2(a.y);
                    xx[r][2] = rep2(b.x); xx[r][3] = rep2(b.y);
                }

#pragma unroll
                for (int kd = 0; kd < 3; kd++) {
#pragma unroll
                    for (int kw = 0; kw < 3; kw++) {
                        const int pos = ci * 27 + kd * 9 + kh * 3 + kw;
                        const ulonglong2* wr2 =
                            (const ulonglong2*)&wsp[pos * 8 + cg * 4];
                        const ulonglong2 w01 = wr2[0];
                        const ulonglong2 w23 = wr2[1];
                        const ull wv[4] = { w01.x, w01.y, w23.x, w23.y };
#pragma unroll
                        for (int pr = 0; pr < 4; pr++) {
#pragma unroll
                            for (int d = 0; d < 4; d++) {
                                fma2(acc[d][pr][0], xx[kd + d][kw],     wv[pr]);
                                fma2(acc[d][pr][1], xx[kd + d][kw + 1], wv[pr]);
                            }
                        }
                    }
                }
            }
        }

#pragma unroll
        for (int d = 0; d < 4; d++)
#pragma unroll
            for (int pr = 0; pr < 4; pr++) {
#pragma unroll
                for (int p = 0; p < 2; p++) {
                    const float2 v = unpk(acc[d][pr][p]);
                    mval[p][2 * pr]     = fminf(mval[p][2 * pr],     v.x);
                    mval[p][2 * pr + 1] = fminf(mval[p][2 * pr + 1], v.y);
                }
            }
    }

    // bias + softmax over 16 channels per pixel, split across 2 threads (cg)
    float v[2][8];
    float2 mx = make_float2(-3.402823466e38f, -3.402823466e38f);
#pragma unroll
    for (int c = 0; c < 8; c++) {
        v[0][c] = mval[0][c] + bsh[cg * 8 + c];
        v[1][c] = mval[1][c] + bsh[cg * 8 + c];
        mx.x = fmaxf(mx.x, v[0][c]);
        mx.y = fmaxf(mx.y, v[1][c]);
    }
    sred[cg][hs][lane] = mx;
    __syncthreads();
    {
        const float2 a = sred[0][hs][lane];
        const float2 b = sred[1][hs][lane];
        mx.x = fmaxf(a.x, b.x);
        mx.y = fmaxf(a.y, b.y);
    }
    __syncthreads();

    float2 s = make_float2(0.f, 0.f);
#pragma unroll
    for (int c = 0; c < 8; c++) {
        v[0][c] = __expf(v[0][c] - mx.x);
        v[1][c] = __expf(v[1][c] - mx.y);
        s.x += v[0][c];
        s.y += v[1][c];
    }
    sred[cg][hs][lane] = s;
    __syncthreads();
    float2 inv;
    {
        const float2 a = sred[0][hs][lane];
        const float2 b = sred[1][hs][lane];
        inv.x = 1.0f / (a.x + b.x);
        inv.y = 1.0f / (a.y + b.y);
    }

    // adjacent w outputs -> float2 stores (offset even => 8B aligned)
    const int hw = h * OW + w0;
#pragma unroll
    for (int c = 0; c < 8; c++) {
        float2 o;
        o.x = v[0][c] * inv.x;
        o.y = v[1][c] * inv.y;
        *(float2*)&out[(size_t)(n * COUT + cg * 8 + c) * (OH * OW) + hw] = o;
    }
}

extern "C" void kernel_launch(void* const* d_in, const int* in_sizes, int n_in,
                              void* d_out, int out_size)
{
    const float* x    = (const float*)d_in[0];  // [16,3,64,64,64]
    const float* wgt  = (const float*)d_in[1];  // [16,3,3,3,3]
    const float* bias = (const float*)d_in[2];  // [16]
    float* out = (float*)d_out;                 // [16,16,62,62]

    dim3 grid(31, 16);   // (h-pair, n)
    dim3 block(128);     // 32 w-pair lanes x 2 channel groups x 2 h rows
    fused_conv_min_softmax<<<grid, block>>>(x, wgt, bias, out);
}